// round 1
// baseline (speedup 1.0000x reference)
#include <cuda_runtime.h>

#define B_ 4
#define N_ 2048
#define IND_ 256
#define H_ 4
#define D_ 64
#define HD_ 256
#define M_ (B_*N_)
#define NEG_SLOPE 0.2f

// Scratch (static __device__ arrays; no allocation allowed)
__device__ float g_h[M_*HD_];        // 32 MB: h = x @ W, layout [B*N][H*D]
__device__ float g_src[M_*H_];
__device__ float g_dst[M_*H_];
__device__ unsigned g_maxdst[B_*H_]; // order-preserving-encoded float max

__global__ void k_init() {
    int t = threadIdx.x;
    if (t < B_*H_) g_maxdst[t] = 0u;
}

// ---------------------------------------------------------------------------
// Kernel 1: h = x @ W   (8192x256 @ 256x256), 64x64 tiles, 4x4 micro-kernel
// ---------------------------------------------------------------------------
__global__ __launch_bounds__(256) void k_gemm(const float* __restrict__ x,
                                              const float* __restrict__ W) {
    __shared__ float As[16][68];  // A transposed: As[k][m], pad 68 (272B, 16B-aligned rows)
    __shared__ float Bs[16][68];  // Bs[k][n]
    const int t  = threadIdx.x;
    const int m0 = blockIdx.x * 64;
    const int n0 = blockIdx.y * 64;
    const int tq = t >> 4, td = t & 15;
    const int am = t >> 2, ak4 = (t & 3) << 2;
    const int bk = t >> 4, bn4 = (t & 15) << 2;

    float acc[4][4];
    #pragma unroll
    for (int i = 0; i < 4; i++)
        #pragma unroll
        for (int j = 0; j < 4; j++) acc[i][j] = 0.f;

    for (int k0 = 0; k0 < IND_; k0 += 16) {
        float4 av = *(const float4*)(x + (m0 + am) * IND_ + k0 + ak4);
        float4 bv = *(const float4*)(W + (k0 + bk) * HD_ + n0 + bn4);
        __syncthreads();
        As[ak4 + 0][am] = av.x;
        As[ak4 + 1][am] = av.y;
        As[ak4 + 2][am] = av.z;
        As[ak4 + 3][am] = av.w;
        *(float4*)&Bs[bk][bn4] = bv;
        __syncthreads();
        #pragma unroll
        for (int k = 0; k < 16; k++) {
            float a0[4], b0[4];
            *(float4*)a0 = *(const float4*)&As[k][tq << 2];
            *(float4*)b0 = *(const float4*)&Bs[k][td << 2];
            #pragma unroll
            for (int i = 0; i < 4; i++)
                #pragma unroll
                for (int j = 0; j < 4; j++)
                    acc[i][j] = fmaf(a0[i], b0[j], acc[i][j]);
        }
    }
    #pragma unroll
    for (int i = 0; i < 4; i++)
        *(float4*)(g_h + (m0 + (tq << 2) + i) * HD_ + n0 + (td << 2)) = *(float4*)acc[i];
}

// ---------------------------------------------------------------------------
// Kernel 2: src/dst per (b,n,h) + per-(b,h) max of dst (encoded atomicMax)
// One block per node row, one warp per head.
// ---------------------------------------------------------------------------
__global__ __launch_bounds__(128) void k_srcdst(const float* __restrict__ a_src,
                                                const float* __restrict__ a_dst) {
    const int row  = blockIdx.x;            // 0..M_-1
    const int h    = threadIdx.x >> 5;
    const int lane = threadIdx.x & 31;
    const float* hp = g_h + row * HD_ + h * D_;
    float v0 = hp[lane], v1 = hp[lane + 32];
    float s = v0 * a_src[h * D_ + lane] + v1 * a_src[h * D_ + lane + 32];
    float d = v0 * a_dst[h * D_ + lane] + v1 * a_dst[h * D_ + lane + 32];
    #pragma unroll
    for (int o = 16; o; o >>= 1) {
        s += __shfl_xor_sync(0xffffffffu, s, o);
        d += __shfl_xor_sync(0xffffffffu, d, o);
    }
    if (lane == 0) {
        g_src[row * H_ + h] = s;
        g_dst[row * H_ + h] = d;
        unsigned bits = __float_as_uint(d);
        unsigned enc  = (d >= 0.f) ? (bits | 0x80000000u) : ~bits;
        int b = row >> 11;  // N_ = 2048
        atomicMax(&g_maxdst[b * H_ + h], enc);
    }
}

// ---------------------------------------------------------------------------
// Kernel 3: fused masked-softmax attention + AV.
// Block = (query tile of 64) x (b,h). Key chunks of 64 rows staged in smem.
// Single-pass softmax: exponents shifted by per-row upper bound C_i, so the
// AV accumulation is a plain 64x64x64 smem GEMM per chunk (4x4 micro-kernel).
// ---------------------------------------------------------------------------
__global__ __launch_bounds__(256) void k_attn(const int* __restrict__ A_mask,
                                              float* __restrict__ out) {
    __shared__ float Ks[64][64];   // key tile: h rows for this head
    __shared__ float Pt[64][68];   // P transposed [j][q], pad 68 for aligned LDS.128
    __shared__ float sDst[64];
    __shared__ float sSrc[64];
    __shared__ float sC[64];
    __shared__ float sLsum[64];

    const int t    = threadIdx.x;
    const int w    = t >> 5, lane = t & 31;
    const int qt0  = blockIdx.x * 64;
    const int bh   = blockIdx.y;
    const int b    = bh >> 2, hh = bh & 3;
    const int rowbase = b * N_;

    unsigned enc = g_maxdst[bh];
    float mdst = (enc & 0x80000000u) ? __uint_as_float(enc & 0x7fffffffu)
                                     : __uint_as_float(~enc);

    if (t < 64) {
        float s = g_src[(rowbase + qt0 + t) * H_ + hh];
        sSrc[t] = s;
        float l = s + mdst;                       // upper bound on src_i + dst_j
        sC[t] = (l >= 0.f) ? l : NEG_SLOPE * l;   // lr is monotone -> valid bound
    }

    float lsum_r[8];
    #pragma unroll
    for (int r = 0; r < 8; r++) lsum_r[r] = 0.f;
    float acc[4][4];
    #pragma unroll
    for (int i = 0; i < 4; i++)
        #pragma unroll
        for (int c = 0; c < 4; c++) acc[i][c] = 0.f;

    const int tq = t >> 4, td = t & 15;  // micro-kernel: q0 = tq*4, d0 = td*4

    for (int j0 = 0; j0 < N_; j0 += 64) {
        __syncthreads();  // protect Ks/Pt from previous chunk's GEMM reads
        // Phase 1: stage key tile + dst values
        #pragma unroll
        for (int p = 0; p < 4; p++) {
            int idx = p * 256 + t;
            int jr  = idx >> 4;
            int d4  = (idx & 15) << 2;
            *(float4*)&Ks[jr][d4] =
                *(const float4*)(g_h + (rowbase + j0 + jr) * HD_ + hh * D_ + d4);
        }
        if (t < 64) sDst[t] = g_dst[(rowbase + j0 + t) * H_ + hh];
        __syncthreads();

        // Phase 2: P tile. Warp w owns query rows w*8 .. w*8+7; lane covers j=lane, lane+32.
        float d0v = sDst[lane], d1v = sDst[lane + 32];
        #pragma unroll
        for (int r = 0; r < 8; r++) {
            int q = (w << 3) + r;
            float srcv = sSrc[q];
            float C    = sC[q];
            const int* mrow = A_mask + (qt0 + q) * N_ + j0;
            int m0v = mrow[lane];
            int m1v = mrow[lane + 32];
            float l0 = srcv + d0v;
            float l1 = srcv + d1v;
            l0 = (l0 >= 0.f) ? l0 : NEG_SLOPE * l0;
            l1 = (l1 >= 0.f) ? l1 : NEG_SLOPE * l1;
            float e0 = m0v ? __expf(l0 - C) : 0.f;
            float e1 = m1v ? __expf(l1 - C) : 0.f;
            lsum_r[r] += e0 + e1;
            Pt[lane][q]      = e0;
            Pt[lane + 32][q] = e1;
        }
        __syncthreads();

        // Phase 3: acc += Pt^T @ Ks  (64x64x64 tile GEMM, 4x4 per thread)
        #pragma unroll 8
        for (int j = 0; j < 64; j++) {
            float p4[4], k4[4];
            *(float4*)p4 = *(const float4*)&Pt[j][tq << 2];
            *(float4*)k4 = *(const float4*)&Ks[j][td << 2];
            #pragma unroll
            for (int i = 0; i < 4; i++)
                #pragma unroll
                for (int c = 0; c < 4; c++)
                    acc[i][c] = fmaf(p4[i], k4[c], acc[i][c]);
        }
    }

    // Row-sum reduction (each warp owned the same rows across all chunks)
    #pragma unroll
    for (int r = 0; r < 8; r++) {
        float v = lsum_r[r];
        #pragma unroll
        for (int o = 16; o; o >>= 1) v += __shfl_xor_sync(0xffffffffu, v, o);
        if (lane == 0) sLsum[(w << 3) + r] = v;
    }
    __syncthreads();

    // Epilogue: normalize + ELU + store
    #pragma unroll
    for (int i = 0; i < 4; i++) {
        int q = (tq << 2) + i;
        float inv = 1.f / sLsum[q];
        float v0 = acc[i][0] * inv;
        float v1 = acc[i][1] * inv;
        float v2 = acc[i][2] * inv;
        float v3 = acc[i][3] * inv;
        float4 o;
        o.x = (v0 > 0.f) ? v0 : expm1f(v0);
        o.y = (v1 > 0.f) ? v1 : expm1f(v1);
        o.z = (v2 > 0.f) ? v2 : expm1f(v2);
        o.w = (v3 > 0.f) ? v3 : expm1f(v3);
        *(float4*)(out + (rowbase + qt0 + q) * HD_ + hh * D_ + (td << 2)) = o;
    }
}

// ---------------------------------------------------------------------------
extern "C" void kernel_launch(void* const* d_in, const int* in_sizes, int n_in,
                              void* d_out, int out_size) {
    const float* x      = (const float*)d_in[0];
    const int*   A_mask = (const int*)d_in[1];
    const float* W      = (const float*)d_in[2];
    const float* a_src  = (const float*)d_in[3];
    const float* a_dst  = (const float*)d_in[4];
    float* out = (float*)d_out;

    k_init<<<1, 32>>>();
    k_gemm<<<dim3(M_ / 64, HD_ / 64), 256>>>(x, W);
    k_srcdst<<<M_, 128>>>(a_src, a_dst);
    k_attn<<<dim3(N_ / 64, B_ * H_), 256>>>(A_mask, out);
}

// round 2
// speedup vs baseline: 1.2610x; 1.2610x over previous
#include <cuda_runtime.h>
#include <cstdint>

#define B_ 4
#define N_ 2048
#define IND_ 256
#define H_ 4
#define D_ 64
#define HD_ 256
#define M_ (B_*N_)
#define NEG_SLOPE 0.2f
#define LOG2E 1.4426950408889634f

#define QT 256   // query tile per block
#define JT 64    // key chunk

// Scratch (static __device__ arrays; no allocation allowed)
__device__ float g_h[M_*HD_];        // 32 MB: h = x @ W, layout [B*N][H*D]
__device__ float g_src[M_*H_];
__device__ float g_dst[M_*H_];
__device__ unsigned g_maxdst[B_*H_]; // order-preserving-encoded float max

__global__ void k_init() {
    int t = threadIdx.x;
    if (t < B_*H_) g_maxdst[t] = 0u;
}

// ---------------------------------------------------------------------------
// Kernel 1: h = x @ W   (8192x256 @ 256x256), 64x64 tiles, 4x4 micro-kernel
// ---------------------------------------------------------------------------
__global__ __launch_bounds__(256) void k_gemm(const float* __restrict__ x,
                                              const float* __restrict__ W) {
    __shared__ float As[16][68];
    __shared__ float Bs[16][68];
    const int t  = threadIdx.x;
    const int m0 = blockIdx.x * 64;
    const int n0 = blockIdx.y * 64;
    const int tq = t >> 4, td = t & 15;
    const int am = t >> 2, ak4 = (t & 3) << 2;
    const int bk = t >> 4, bn4 = (t & 15) << 2;

    float acc[4][4];
    #pragma unroll
    for (int i = 0; i < 4; i++)
        #pragma unroll
        for (int j = 0; j < 4; j++) acc[i][j] = 0.f;

    for (int k0 = 0; k0 < IND_; k0 += 16) {
        float4 av = *(const float4*)(x + (m0 + am) * IND_ + k0 + ak4);
        float4 bv = *(const float4*)(W + (k0 + bk) * HD_ + n0 + bn4);
        __syncthreads();
        As[ak4 + 0][am] = av.x;
        As[ak4 + 1][am] = av.y;
        As[ak4 + 2][am] = av.z;
        As[ak4 + 3][am] = av.w;
        *(float4*)&Bs[bk][bn4] = bv;
        __syncthreads();
        #pragma unroll
        for (int k = 0; k < 16; k++) {
            float a0[4], b0[4];
            *(float4*)a0 = *(const float4*)&As[k][tq << 2];
            *(float4*)b0 = *(const float4*)&Bs[k][td << 2];
            #pragma unroll
            for (int i = 0; i < 4; i++)
                #pragma unroll
                for (int j = 0; j < 4; j++)
                    acc[i][j] = fmaf(a0[i], b0[j], acc[i][j]);
        }
    }
    #pragma unroll
    for (int i = 0; i < 4; i++)
        *(float4*)(g_h + (m0 + (tq << 2) + i) * HD_ + n0 + (td << 2)) = *(float4*)acc[i];
}

// ---------------------------------------------------------------------------
// Kernel 2: src/dst per (b,n,h) + per-(b,h) max of dst (encoded atomicMax)
// ---------------------------------------------------------------------------
__global__ __launch_bounds__(128) void k_srcdst(const float* __restrict__ a_src,
                                                const float* __restrict__ a_dst) {
    const int row  = blockIdx.x;
    const int h    = threadIdx.x >> 5;
    const int lane = threadIdx.x & 31;
    const float* hp = g_h + row * HD_ + h * D_;
    float v0 = hp[lane], v1 = hp[lane + 32];
    float s = v0 * a_src[h * D_ + lane] + v1 * a_src[h * D_ + lane + 32];
    float d = v0 * a_dst[h * D_ + lane] + v1 * a_dst[h * D_ + lane + 32];
    #pragma unroll
    for (int o = 16; o; o >>= 1) {
        s += __shfl_xor_sync(0xffffffffu, s, o);
        d += __shfl_xor_sync(0xffffffffu, d, o);
    }
    if (lane == 0) {
        g_src[row * H_ + h] = s;
        g_dst[row * H_ + h] = d;
        unsigned bits = __float_as_uint(d);
        unsigned enc  = (d >= 0.f) ? (bits | 0x80000000u) : ~bits;
        int b = row >> 11;
        atomicMax(&g_maxdst[b * H_ + h], enc);
    }
}

// ---------------------------------------------------------------------------
// Kernel 3: fused masked-softmax attention + AV, FFMA2 (f32x2) micro-kernel.
//
// Block = 256 threads, q-tile 256, one (b,h). Per-thread 8q x 8d outputs held
// as f32x2 pairs along d. Pt layout [q][j] (q-major, 64 floats/row) with XOR
// granule swizzle (jb ^ (q>>3 & 3)); Ks stored with even/odd granule
// permutation so each thread's two 16B k-reads hit distinct banks.
// ---------------------------------------------------------------------------
__device__ __forceinline__ float ex2f(float x) {
    float r; asm("ex2.approx.f32 %0, %1;" : "=f"(r) : "f"(x)); return r;
}
__device__ __forceinline__ unsigned long long dupf(float v) {
    unsigned long long r;
    unsigned u = __float_as_uint(v);
    asm("mov.b64 %0, {%1, %1};" : "=l"(r) : "r"(u));
    return r;
}
#define FFMA2(d, a, b) asm("fma.rn.f32x2 %0, %1, %2, %0;" : "+l"(d) : "l"(a), "l"(b))

// smem float offsets
#define SM_KS   0
#define SM_PT   (JT * 64)                  // 4096
#define SM_DST  (SM_PT + QT * 64)          // 4096 + 16384
#define SM_SRC  (SM_DST + JT)
#define SM_CL   (SM_SRC + QT)
#define SM_LS   (SM_CL + QT)
#define SM_TOT  (SM_LS + QT)               // floats

__global__ __launch_bounds__(256, 1) void k_attn(const int* __restrict__ A_mask,
                                                 float* __restrict__ out) {
    extern __shared__ float sm[];
    float* Ks    = sm + SM_KS;
    float* Pt    = sm + SM_PT;
    float* sDst  = sm + SM_DST;
    float* sSrc  = sm + SM_SRC;
    float* sCl   = sm + SM_CL;
    float* sLsum = sm + SM_LS;

    const int t    = threadIdx.x;
    const int qt0  = blockIdx.x * QT;
    const int bh   = blockIdx.y;
    const int b    = bh >> 2, hh = bh & 3;
    const int rowbase = b * N_;
    const int tq = t >> 3, td = t & 7;   // GEMM mapping: q = tq*8+i, d = td*8+2c(+1)

    unsigned enc = g_maxdst[bh];
    float mdst = (enc & 0x80000000u) ? __uint_as_float(enc & 0x7fffffffu)
                                     : __uint_as_float(~enc);
    {
        float s = g_src[(rowbase + qt0 + t) * H_ + hh];
        sSrc[t] = s;
        float l = s + mdst;                       // upper bound on src_i + dst_j
        float C = fmaxf(l, NEG_SLOPE * l);        // leaky_relu monotone -> bound
        sCl[t] = C * LOG2E;
    }

    float lsum[16];
    #pragma unroll
    for (int p = 0; p < 16; p++) lsum[p] = 0.f;
    unsigned long long acc[8][4];
    #pragma unroll
    for (int i = 0; i < 8; i++)
        #pragma unroll
        for (int c = 0; c < 4; c++) acc[i][c] = 0ull;

    for (int j0 = 0; j0 < N_; j0 += JT) {
        __syncthreads();
        // ---- Phase 1: stage Ks (granule-permuted) + sDst ----
        {
            int jr = t >> 4;         // 0..15
            int g  = t & 15;         // source granule (4 floats)
            int gp = (g >> 1) + ((g & 1) << 3);   // even g -> g/2, odd g -> 8+g/2
            #pragma unroll
            for (int p = 0; p < 4; p++) {
                int j = jr + (p << 4);
                float4 v = *(const float4*)(g_h + (rowbase + j0 + j) * HD_ + hh * D_ + (g << 2));
                *(float4*)&Ks[j * 64 + (gp << 2)] = v;
            }
            if (t < JT) sDst[t] = g_dst[(rowbase + j0 + t) * H_ + hh];
        }
        __syncthreads();

        // ---- Phase 2: P tile [q][j] with XOR swizzle; coalesced mask loads ----
        {
            const int j4 = (t & 15) << 2;
            const int qb = t >> 4;
            float4 dv = *(const float4*)&sDst[j4];
            #pragma unroll
            for (int p = 0; p < 16; p++) {
                int q = qb + (p << 4);
                int4 m = *(const int4*)(A_mask + (qt0 + q) * N_ + j0 + j4);
                float s  = sSrc[q];
                float Cl = sCl[q];
                float l0 = s + dv.x, l1 = s + dv.y, l2 = s + dv.z, l3 = s + dv.w;
                l0 = fmaxf(l0, NEG_SLOPE * l0);
                l1 = fmaxf(l1, NEG_SLOPE * l1);
                l2 = fmaxf(l2, NEG_SLOPE * l2);
                l3 = fmaxf(l3, NEG_SLOPE * l3);
                float e0 = ex2f(fmaf(l0, LOG2E, -Cl));
                float e1 = ex2f(fmaf(l1, LOG2E, -Cl));
                float e2 = ex2f(fmaf(l2, LOG2E, -Cl));
                float e3 = ex2f(fmaf(l3, LOG2E, -Cl));
                e0 = m.x ? e0 : 0.f;
                e1 = m.y ? e1 : 0.f;
                e2 = m.z ? e2 : 0.f;
                e3 = m.w ? e3 : 0.f;
                lsum[p] += (e0 + e1) + (e2 + e3);
                int gp = (t & 15) ^ ((q >> 3) & 3);
                *(float4*)&Pt[q * 64 + (gp << 2)] = make_float4(e0, e1, e2, e3);
            }
        }
        __syncthreads();

        // ---- Phase 3: acc += P^T-tile GEMM, FFMA2 pairs along d ----
        {
            #pragma unroll
            for (int jb = 0; jb < 16; jb++) {
                float4 p4[8];
                int gq = jb ^ (tq & 3);
                #pragma unroll
                for (int i = 0; i < 8; i++)
                    p4[i] = *(const float4*)&Pt[(tq * 8 + i) * 64 + (gq << 2)];
                #pragma unroll
                for (int jj = 0; jj < 4; jj++) {
                    int j = (jb << 2) + jj;
                    ulonglong2 kl = *(const ulonglong2*)&Ks[j * 64 + (td << 2)];        // d = 8td..8td+3
                    ulonglong2 kh = *(const ulonglong2*)&Ks[j * 64 + 32 + (td << 2)];   // d = 8td+4..8td+7
                    #pragma unroll
                    for (int i = 0; i < 8; i++) {
                        float pv = (jj == 0) ? p4[i].x : (jj == 1) ? p4[i].y
                                 : (jj == 2) ? p4[i].z : p4[i].w;
                        unsigned long long pd = dupf(pv);
                        FFMA2(acc[i][0], pd, kl.x);
                        FFMA2(acc[i][1], pd, kl.y);
                        FFMA2(acc[i][2], pd, kh.x);
                        FFMA2(acc[i][3], pd, kh.y);
                    }
                }
            }
        }
    }

    // ---- lsum reduction: 16 consecutive threads share each q ----
    #pragma unroll
    for (int p = 0; p < 16; p++) {
        float v = lsum[p];
        v += __shfl_xor_sync(0xffffffffu, v, 1);
        v += __shfl_xor_sync(0xffffffffu, v, 2);
        v += __shfl_xor_sync(0xffffffffu, v, 4);
        v += __shfl_xor_sync(0xffffffffu, v, 8);
        if ((t & 15) == 0) sLsum[(t >> 4) + (p << 4)] = v;
    }
    __syncthreads();

    // ---- Epilogue: normalize + ELU + store ----
    #pragma unroll
    for (int i = 0; i < 8; i++) {
        int q = tq * 8 + i;
        float inv = 1.f / sLsum[q];
        float v[8];
        #pragma unroll
        for (int c = 0; c < 4; c++) {
            unsigned lo, hi;
            asm("mov.b64 {%0, %1}, %2;" : "=r"(lo), "=r"(hi) : "l"(acc[i][c]));
            v[2*c]   = __uint_as_float(lo) * inv;
            v[2*c+1] = __uint_as_float(hi) * inv;
        }
        #pragma unroll
        for (int c = 0; c < 8; c++)
            v[c] = (v[c] > 0.f) ? v[c] : expm1f(v[c]);
        float* op = out + (rowbase + qt0 + q) * HD_ + hh * D_ + td * 8;
        *(float4*)op       = make_float4(v[0], v[1], v[2], v[3]);
        *(float4*)(op + 4) = make_float4(v[4], v[5], v[6], v[7]);
    }
}

// ---------------------------------------------------------------------------
extern "C" void kernel_launch(void* const* d_in, const int* in_sizes, int n_in,
                              void* d_out, int out_size) {
    const float* x      = (const float*)d_in[0];
    const int*   A_mask = (const int*)d_in[1];
    const float* W      = (const float*)d_in[2];
    const float* a_src  = (const float*)d_in[3];
    const float* a_dst  = (const float*)d_in[4];
    float* out = (float*)d_out;

    cudaFuncSetAttribute(k_attn, cudaFuncAttributeMaxDynamicSharedMemorySize,
                         SM_TOT * (int)sizeof(float));

    k_init<<<1, 32>>>();
    k_gemm<<<dim3(M_ / 64, HD_ / 64), 256>>>(x, W);
    k_srcdst<<<M_, 128>>>(a_src, a_dst);
    k_attn<<<dim3(N_ / QT, B_ * H_), 256, SM_TOT * (int)sizeof(float)>>>(A_mask, out);
}